// round 1
// baseline (speedup 1.0000x reference)
#include <cuda_runtime.h>
#include <math.h>

#define N_NODES 100000
#define N_EDGES 3200000
#define TOT_SLOTS (N_EDGES + N_NODES)
#define SCAN_BLOCK 1024
#define SCAN_NBLK ((N_NODES + SCAN_BLOCK - 1) / SCAN_BLOCK)

// Scratch (device globals: allocation-free rule)
__device__ float g_xall[(size_t)N_NODES * 32];   // [n][level 0..3][c 0..7], 128B/node
__device__ float g_dinv[N_NODES];
__device__ int   g_deg[N_NODES];
__device__ int   g_off[N_NODES + 1];
__device__ int   g_cursor[N_NODES];
__device__ int   g_csr[TOT_SLOTS];
__device__ int   g_bsum[SCAN_NBLK];

// ---------------- CSR build ----------------

__global__ void init_kernel() {
    int n = blockIdx.x * blockDim.x + threadIdx.x;
    if (n < N_NODES) { g_deg[n] = 1; g_cursor[n] = 0; }
}

__global__ void count_kernel(const int* __restrict__ dst) {
    int e = blockIdx.x * blockDim.x + threadIdx.x;
    if (e < N_EDGES) atomicAdd(&g_deg[dst[e]], 1);
}

__global__ void scan1_kernel() {
    __shared__ int sh[SCAN_BLOCK];
    int i = blockIdx.x * SCAN_BLOCK + threadIdx.x;
    int v = (i < N_NODES) ? g_deg[i] : 0;
    sh[threadIdx.x] = v;
    __syncthreads();
    #pragma unroll
    for (int o = 1; o < SCAN_BLOCK; o <<= 1) {
        int t = 0;
        if ((int)threadIdx.x >= o) t = sh[threadIdx.x - o];
        __syncthreads();
        sh[threadIdx.x] += t;
        __syncthreads();
    }
    if (i < N_NODES) g_off[i] = sh[threadIdx.x] - v;  // exclusive, per-block
    if (threadIdx.x == SCAN_BLOCK - 1) g_bsum[blockIdx.x] = sh[SCAN_BLOCK - 1];
}

__global__ void scan2_kernel() {
    if (threadIdx.x == 0 && blockIdx.x == 0) {
        int s = 0;
        for (int b = 0; b < SCAN_NBLK; b++) { int t = g_bsum[b]; g_bsum[b] = s; s += t; }
    }
}

__global__ void scan3_kernel() {
    int i = blockIdx.x * SCAN_BLOCK + threadIdx.x;
    if (i < N_NODES) g_off[i] += g_bsum[blockIdx.x];
    if (i == 0) g_off[N_NODES] = TOT_SLOTS;
}

__global__ void fill_self_kernel() {
    int n = blockIdx.x * blockDim.x + threadIdx.x;
    if (n < N_NODES) {
        g_csr[g_off[n]] = n;                       // self-loop slot first
        g_dinv[n] = rsqrtf((float)g_deg[n]);
    }
}

__global__ void fill_edges_kernel(const int* __restrict__ src, const int* __restrict__ dst) {
    int e = blockIdx.x * blockDim.x + threadIdx.x;
    if (e < N_EDGES) {
        int d = dst[e];
        int p = g_off[d] + 1 + atomicAdd(&g_cursor[d], 1);
        g_csr[p] = src[e];
    }
}

// ---------------- input MLP: h0 = relu([emb|x] @ W1 + b1) ----------------

__global__ void mlp0_kernel(const float* __restrict__ x,
                            const int* __restrict__ node_index,
                            const float* __restrict__ emb,
                            const float* __restrict__ W1,
                            const float* __restrict__ b1) {
    __shared__ float sW[24 * 8 + 8];
    int t = threadIdx.x;
    if (t < 192) sW[t] = W1[t];
    if (t < 8) sW[192 + t] = b1[t];
    __syncthreads();
    int n = blockIdx.x * blockDim.x + t;
    if (n >= N_NODES) return;
    float in[24];
    int idx = node_index[n];
    #pragma unroll
    for (int j = 0; j < 8; j++) in[j] = emb[(size_t)idx * 8 + j];
    #pragma unroll
    for (int j = 0; j < 16; j++) in[8 + j] = x[(size_t)n * 16 + j];
    float* outp = g_xall + (size_t)n * 32;
    #pragma unroll
    for (int c = 0; c < 8; c++) {
        float s = sW[192 + c];
        #pragma unroll
        for (int j = 0; j < 24; j++) s = fmaf(in[j], sW[j * 8 + c], s);
        outp[c] = fmaxf(s, 0.0f);
    }
}

// ---------------- DNA conv layer (warp per node) ----------------

template <int L>
__global__ void __launch_bounds__(256) conv_kernel(
    const float* __restrict__ Wq, const float* __restrict__ Bq,
    const float* __restrict__ Wk, const float* __restrict__ Bk,
    const float* __restrict__ Wv, const float* __restrict__ Bv)
{
    int gw = (blockIdx.x * blockDim.x + threadIdx.x) >> 5;
    int lane = threadIdx.x & 31;
    if (gw >= N_NODES) return;
    int n = gw;

    float wk[8], bk[8], wv[8], bv[8];
    #pragma unroll
    for (int c = 0; c < 8; c++) {
        wk[c] = __ldg(Wk + c); bk[c] = __ldg(Bk + c);
        wv[c] = __ldg(Wv + c); bv[c] = __ldg(Bv + c);
    }
    // q for this node from latest level (L-1), grouped linear == per-channel affine
    const float* xn = g_xall + (size_t)n * 32 + (L - 1) * 8;
    float q[8];
    #pragma unroll
    for (int c = 0; c < 8; c++) q[c] = fmaf(xn[c], __ldg(Wq + c), __ldg(Bq + c));

    float dn = g_dinv[n];
    float acc[8] = {0.f, 0.f, 0.f, 0.f, 0.f, 0.f, 0.f, 0.f};

    int beg = g_off[n], end = g_off[n + 1];
    for (int e = beg + lane; e < end; e += 32) {
        int s = g_csr[e];
        float w = dn * g_dinv[s];
        float xv[L][8];
        const float4* xsp = (const float4*)(g_xall + (size_t)s * 32);
        #pragma unroll
        for (int l = 0; l < L; l++) {
            float4 a = xsp[l * 2];
            float4 b = xsp[l * 2 + 1];
            xv[l][0] = a.x; xv[l][1] = a.y; xv[l][2] = a.z; xv[l][3] = a.w;
            xv[l][4] = b.x; xv[l][5] = b.y; xv[l][6] = b.z; xv[l][7] = b.w;
        }
        // scores: per head, dot(q, k) over d=4, scaled by 1/sqrt(4)
        float at[2][L];
        #pragma unroll
        for (int h = 0; h < 2; h++) {
            float sc[L];
            #pragma unroll
            for (int l = 0; l < L; l++) {
                float s_ = 0.0f;
                #pragma unroll
                for (int d = 0; d < 4; d++) {
                    int c = h * 4 + d;
                    s_ = fmaf(q[c], fmaf(xv[l][c], wk[c], bk[c]), s_);
                }
                sc[l] = s_ * 0.5f;
            }
            float m = sc[0];
            #pragma unroll
            for (int l = 1; l < L; l++) m = fmaxf(m, sc[l]);
            float sm = 0.0f;
            #pragma unroll
            for (int l = 0; l < L; l++) { at[h][l] = __expf(sc[l] - m); sm += at[h][l]; }
            float inv = 1.0f / sm;
            #pragma unroll
            for (int l = 0; l < L; l++) at[h][l] *= inv;
        }
        // message: sum_l attn * v, per channel; then * norm
        #pragma unroll
        for (int c = 0; c < 8; c++) {
            int h = c >> 2;
            float m_ = 0.0f;
            #pragma unroll
            for (int l = 0; l < L; l++) m_ = fmaf(at[h][l], fmaf(xv[l][c], wv[c], bv[c]), m_);
            acc[c] = fmaf(w, m_, acc[c]);
        }
    }
    // warp tree-reduce 8 channels
    #pragma unroll
    for (int o = 16; o; o >>= 1) {
        #pragma unroll
        for (int c = 0; c < 8; c++) acc[c] += __shfl_xor_sync(0xffffffffu, acc[c], o);
    }
    if (lane == 0) {
        float* outp = g_xall + (size_t)n * 32 + L * 8;
        float4 r0 = make_float4(fmaxf(acc[0], 0.f), fmaxf(acc[1], 0.f),
                                fmaxf(acc[2], 0.f), fmaxf(acc[3], 0.f));
        float4 r1 = make_float4(fmaxf(acc[4], 0.f), fmaxf(acc[5], 0.f),
                                fmaxf(acc[6], 0.f), fmaxf(acc[7], 0.f));
        ((float4*)outp)[0] = r0;
        ((float4*)outp)[1] = r1;
    }
}

// ---------------- output head: logits + log_softmax ----------------

__global__ void out_kernel(const float* __restrict__ W2,
                           const float* __restrict__ b2,
                           float* __restrict__ out) {
    int n = blockIdx.x * blockDim.x + threadIdx.x;
    if (n >= N_NODES) return;
    const float* xl = g_xall + (size_t)n * 32 + 24;  // level 3
    float z0 = __ldg(b2 + 0), z1 = __ldg(b2 + 1);
    #pragma unroll
    for (int c = 0; c < 8; c++) {
        float v = xl[c];
        z0 = fmaf(v, __ldg(W2 + c * 2 + 0), z0);
        z1 = fmaf(v, __ldg(W2 + c * 2 + 1), z1);
    }
    float m = fmaxf(z0, z1);
    float lse = m + logf(expf(z0 - m) + expf(z1 - m));
    out[(size_t)n * 2 + 0] = z0 - lse;
    out[(size_t)n * 2 + 1] = z1 - lse;
}

// ---------------- launch ----------------

extern "C" void kernel_launch(void* const* d_in, const int* in_sizes, int n_in,
                              void* d_out, int out_size) {
    const float* x        = (const float*)d_in[0];
    const int*   nidx     = (const int*)  d_in[1];
    // d_in[2] node_one_hot: unused by reference
    const int*   eidx     = (const int*)  d_in[3];   // [2, E]
    // d_in[4] edge_weight: unused by reference
    const float* emb      = (const float*)d_in[5];
    const float* W1       = (const float*)d_in[6];
    const float* b1       = (const float*)d_in[7];
    const float* Wq       = (const float*)d_in[8];
    const float* bq       = (const float*)d_in[9];
    const float* Wk       = (const float*)d_in[10];
    const float* bk       = (const float*)d_in[11];
    const float* Wv       = (const float*)d_in[12];
    const float* bv       = (const float*)d_in[13];
    const float* W2       = (const float*)d_in[14];
    const float* b2       = (const float*)d_in[15];
    float* out = (float*)d_out;

    const int* src = eidx;
    const int* dst = eidx + N_EDGES;

    int nb_n = (N_NODES + 255) / 256;
    int nb_e = (N_EDGES + 255) / 256;

    init_kernel<<<nb_n, 256>>>();
    count_kernel<<<nb_e, 256>>>(dst);
    scan1_kernel<<<SCAN_NBLK, SCAN_BLOCK>>>();
    scan2_kernel<<<1, 32>>>();
    scan3_kernel<<<SCAN_NBLK, SCAN_BLOCK>>>();
    fill_self_kernel<<<nb_n, 256>>>();
    fill_edges_kernel<<<nb_e, 256>>>(src, dst);

    mlp0_kernel<<<nb_n, 256>>>(x, nidx, emb, W1, b1);

    int nb_w = (N_NODES * 32 + 255) / 256;  // warp per node
    conv_kernel<1><<<nb_w, 256>>>(Wq + 0,  bq + 0,  Wk + 0,  bk + 0,  Wv + 0,  bv + 0);
    conv_kernel<2><<<nb_w, 256>>>(Wq + 8,  bq + 8,  Wk + 8,  bk + 8,  Wv + 8,  bv + 8);
    conv_kernel<3><<<nb_w, 256>>>(Wq + 16, bq + 16, Wk + 16, bk + 16, Wv + 16, bv + 16);

    out_kernel<<<nb_n, 256>>>(W2, b2, out);
}

// round 2
// speedup vs baseline: 1.2590x; 1.2590x over previous
#include <cuda_runtime.h>
#include <math.h>

#define N_NODES 100000
#define N_EDGES 3200000
#define TOT_SLOTS (N_EDGES + N_NODES)
#define SCAN_BLOCK 1024
#define SCAN_NBLK ((N_NODES + SCAN_BLOCK - 1) / SCAN_BLOCK)   // 98

// Scratch (device globals: allocation-free rule). g_xall: 128B record per node,
// [level 0..3][c 0..7]; all levels of a node share one L1 cache line.
__device__ float4 g_xall[(size_t)N_NODES * 8];
__device__ float  g_dinv[N_NODES];
__device__ int    g_deg[N_NODES];
__device__ int    g_off[N_NODES + 1];
__device__ int    g_cursor[N_NODES];
__device__ int2   g_csr[TOT_SLOTS];     // {src, __float_as_int(dinv[src])}
__device__ int    g_bsum[SCAN_NBLK];

// ---------------- CSR build ----------------

__global__ void init_kernel() {
    int n = blockIdx.x * blockDim.x + threadIdx.x;
    if (n < N_NODES) g_deg[n] = 1;   // self loop
}

__global__ void count_kernel(const int* __restrict__ dst) {
    int e = blockIdx.x * blockDim.x + threadIdx.x;
    if (e < N_EDGES) atomicAdd(&g_deg[dst[e]], 1);
}

__global__ void scan1_kernel() {
    __shared__ int sh[SCAN_BLOCK];
    int i = blockIdx.x * SCAN_BLOCK + threadIdx.x;
    int v = (i < N_NODES) ? g_deg[i] : 0;
    sh[threadIdx.x] = v;
    __syncthreads();
    #pragma unroll
    for (int o = 1; o < SCAN_BLOCK; o <<= 1) {
        int t = 0;
        if ((int)threadIdx.x >= o) t = sh[threadIdx.x - o];
        __syncthreads();
        sh[threadIdx.x] += t;
        __syncthreads();
    }
    if (i < N_NODES) g_off[i] = sh[threadIdx.x] - v;  // exclusive, per-block
    if (threadIdx.x == SCAN_BLOCK - 1) g_bsum[blockIdx.x] = sh[SCAN_BLOCK - 1];
}

__global__ void scan2_kernel() {    // one block, 128 threads, Hillis-Steele
    __shared__ int sh[128];
    int t = threadIdx.x;
    int v = (t < SCAN_NBLK) ? g_bsum[t] : 0;
    sh[t] = v;
    __syncthreads();
    #pragma unroll
    for (int o = 1; o < 128; o <<= 1) {
        int x = 0;
        if (t >= o) x = sh[t - o];
        __syncthreads();
        sh[t] += x;
        __syncthreads();
    }
    if (t < SCAN_NBLK) g_bsum[t] = sh[t] - v;   // exclusive across blocks
}

__global__ void scan3_kernel() {
    int i = blockIdx.x * SCAN_BLOCK + threadIdx.x;
    if (i < N_NODES) g_off[i] += g_bsum[blockIdx.x];
    if (i == 0) g_off[N_NODES] = TOT_SLOTS;
}

__global__ void fill_self_kernel() {
    int n = blockIdx.x * blockDim.x + threadIdx.x;
    if (n < N_NODES) {
        float di = rsqrtf((float)g_deg[n]);
        g_dinv[n] = di;
        int o = g_off[n];
        g_csr[o] = make_int2(n, __float_as_int(di));
        g_cursor[n] = o + 1;
    }
}

__global__ void fill_edges_kernel(const int* __restrict__ src, const int* __restrict__ dst) {
    int e = blockIdx.x * blockDim.x + threadIdx.x;
    if (e < N_EDGES) {
        int s = src[e];
        int d = dst[e];
        int p = atomicAdd(&g_cursor[d], 1);
        g_csr[p] = make_int2(s, __float_as_int(g_dinv[s]));
    }
}

// ---------------- input MLP: h0 = relu([emb|x] @ W1 + b1) ----------------

__global__ void mlp0_kernel(const float* __restrict__ x,
                            const int* __restrict__ node_index,
                            const float* __restrict__ emb,
                            const float* __restrict__ W1,
                            const float* __restrict__ b1) {
    __shared__ float sW[24 * 8 + 8];
    int t = threadIdx.x;
    if (t < 192) sW[t] = W1[t];
    if (t < 8) sW[192 + t] = b1[t];
    __syncthreads();
    int n = blockIdx.x * blockDim.x + t;
    if (n >= N_NODES) return;
    float in[24];
    int idx = node_index[n];
    #pragma unroll
    for (int j = 0; j < 8; j++) in[j] = emb[(size_t)idx * 8 + j];
    #pragma unroll
    for (int j = 0; j < 16; j++) in[8 + j] = x[(size_t)n * 16 + j];
    float o[8];
    #pragma unroll
    for (int c = 0; c < 8; c++) {
        float s = sW[192 + c];
        #pragma unroll
        for (int j = 0; j < 24; j++) s = fmaf(in[j], sW[j * 8 + c], s);
        o[c] = fmaxf(s, 0.0f);
    }
    float4* outp = g_xall + (size_t)n * 8;
    outp[0] = make_float4(o[0], o[1], o[2], o[3]);
    outp[1] = make_float4(o[4], o[5], o[6], o[7]);
}

// ---------------- DNA conv layer: warp per node, shared-staged gathers ----

template <int L>
__global__ void __launch_bounds__(256) conv_kernel(
    const float* __restrict__ Wq, const float* __restrict__ Bq,
    const float* __restrict__ Wk, const float* __restrict__ Bk,
    const float* __restrict__ Wv, const float* __restrict__ Bv)
{
    constexpr int CH = 2 * L;       // 16B chunks per edge (8L floats)
    constexpr int S  = 8 * L + 4;   // smem floats per edge (pad kills conflicts)
    __shared__ float sx[8 * 32 * S];

    int warp = threadIdx.x >> 5, lane = threadIdx.x & 31;
    int n = blockIdx.x * 8 + warp;
    if (n >= N_NODES) return;       // warp-uniform exit
    float* ws = sx + warp * (32 * S);

    float wv[8], bv[8];
    #pragma unroll
    for (int c = 0; c < 8; c++) { wv[c] = __ldg(Wv + c); bv[c] = __ldg(Bv + c); }

    float qk[8];
    float qb0 = 0.0f, qb1 = 0.0f;
    if (L > 1) {
        const float* xn = ((const float*)(g_xall + (size_t)n * 8)) + (L - 1) * 8;
        #pragma unroll
        for (int c = 0; c < 8; c++) {
            float q = fmaf(xn[c], __ldg(Wq + c), __ldg(Bq + c));
            qk[c] = 0.5f * q * __ldg(Wk + c);                 // fold 1/sqrt(d)=0.5
            float qb = 0.5f * q * __ldg(Bk + c);
            if (c < 4) qb0 += qb; else qb1 += qb;
        }
    }

    float dn = g_dinv[n];
    int beg = g_off[n], end = g_off[n + 1];
    float acc[8] = {0.f, 0.f, 0.f, 0.f, 0.f, 0.f, 0.f, 0.f};

    for (int tb = beg; tb < end; tb += 32) {
        int cnt = min(32, end - tb);
        int2 ent = make_int2(0, 0);
        if (lane < cnt) ent = __ldg(&g_csr[tb + lane]);

        // cooperative gather: consecutive lanes fetch consecutive 16B chunks of
        // the SAME edge's record -> ~1 L1 line (wavefront) per edge
        int T = cnt * CH;
        int rounds = (T + 31) >> 5;
        for (int r = 0; r < rounds; r++) {
            int idx = r * 32 + lane;
            int ci = min(idx, T - 1);
            int e = ci / CH, c = ci - e * CH;
            int s = __shfl_sync(0xffffffffu, ent.x, e);
            if (idx < T) {
                float4 v = __ldg(g_xall + (size_t)s * 8 + c);
                *(float4*)(ws + e * S + c * 4) = v;
            }
        }
        __syncwarp();

        if (lane < cnt) {
            float w = dn * __int_as_float(ent.y);
            const float* xe = ws + lane * S;
            float xl[L][8];
            #pragma unroll
            for (int l = 0; l < L; l++) {
                float4 a = *(const float4*)(xe + l * 8);
                float4 b = *(const float4*)(xe + l * 8 + 4);
                xl[l][0] = a.x; xl[l][1] = a.y; xl[l][2] = a.z; xl[l][3] = a.w;
                xl[l][4] = b.x; xl[l][5] = b.y; xl[l][6] = b.z; xl[l][7] = b.w;
            }
            float at[2][L];
            if (L == 1) {
                at[0][0] = 1.0f; at[1][0] = 1.0f;   // softmax over 1 elem
            } else {
                #pragma unroll
                for (int h = 0; h < 2; h++) {
                    float sc[L];
                    #pragma unroll
                    for (int l = 0; l < L; l++) {
                        float s_ = (h == 0) ? qb0 : qb1;
                        #pragma unroll
                        for (int d = 0; d < 4; d++)
                            s_ = fmaf(qk[h * 4 + d], xl[l][h * 4 + d], s_);
                        sc[l] = s_;
                    }
                    float m = sc[0];
                    #pragma unroll
                    for (int l = 1; l < L; l++) m = fmaxf(m, sc[l]);
                    float sm = 0.0f;
                    #pragma unroll
                    for (int l = 0; l < L; l++) { at[h][l] = __expf(sc[l] - m); sm += at[h][l]; }
                    float inv = 1.0f / sm;
                    #pragma unroll
                    for (int l = 0; l < L; l++) at[h][l] *= inv;
                }
            }
            // sum attn = 1  =>  msg_c = bv_c + wv_c * sum_l attn_l * x_l,c
            #pragma unroll
            for (int c = 0; c < 8; c++) {
                int h = c >> 2;
                float t = 0.0f;
                #pragma unroll
                for (int l = 0; l < L; l++) t = fmaf(at[h][l], xl[l][c], t);
                acc[c] = fmaf(w, fmaf(wv[c], t, bv[c]), acc[c]);
            }
        }
        __syncwarp();
    }

    #pragma unroll
    for (int o = 16; o; o >>= 1) {
        #pragma unroll
        for (int c = 0; c < 8; c++) acc[c] += __shfl_xor_sync(0xffffffffu, acc[c], o);
    }
    if (lane == 0) {
        float4* outp = g_xall + (size_t)n * 8 + L * 2;
        outp[0] = make_float4(fmaxf(acc[0], 0.f), fmaxf(acc[1], 0.f),
                              fmaxf(acc[2], 0.f), fmaxf(acc[3], 0.f));
        outp[1] = make_float4(fmaxf(acc[4], 0.f), fmaxf(acc[5], 0.f),
                              fmaxf(acc[6], 0.f), fmaxf(acc[7], 0.f));
    }
}

// ---------------- output head: logits + log_softmax ----------------

__global__ void out_kernel(const float* __restrict__ W2,
                           const float* __restrict__ b2,
                           float* __restrict__ out) {
    int n = blockIdx.x * blockDim.x + threadIdx.x;
    if (n >= N_NODES) return;
    float4 a = __ldg(g_xall + (size_t)n * 8 + 6);
    float4 b = __ldg(g_xall + (size_t)n * 8 + 7);
    float xl[8] = {a.x, a.y, a.z, a.w, b.x, b.y, b.z, b.w};
    float z0 = __ldg(b2 + 0), z1 = __ldg(b2 + 1);
    #pragma unroll
    for (int c = 0; c < 8; c++) {
        z0 = fmaf(xl[c], __ldg(W2 + c * 2 + 0), z0);
        z1 = fmaf(xl[c], __ldg(W2 + c * 2 + 1), z1);
    }
    float m = fmaxf(z0, z1);
    float lse = m + logf(expf(z0 - m) + expf(z1 - m));
    out[(size_t)n * 2 + 0] = z0 - lse;
    out[(size_t)n * 2 + 1] = z1 - lse;
}

// ---------------- launch ----------------

extern "C" void kernel_launch(void* const* d_in, const int* in_sizes, int n_in,
                              void* d_out, int out_size) {
    const float* x    = (const float*)d_in[0];
    const int*   nidx = (const int*)  d_in[1];
    const int*   eidx = (const int*)  d_in[3];   // [2, E]
    const float* emb  = (const float*)d_in[5];
    const float* W1   = (const float*)d_in[6];
    const float* b1   = (const float*)d_in[7];
    const float* Wq   = (const float*)d_in[8];
    const float* bq   = (const float*)d_in[9];
    const float* Wk   = (const float*)d_in[10];
    const float* bk   = (const float*)d_in[11];
    const float* Wv   = (const float*)d_in[12];
    const float* bv   = (const float*)d_in[13];
    const float* W2   = (const float*)d_in[14];
    const float* b2   = (const float*)d_in[15];
    float* out = (float*)d_out;

    const int* src = eidx;
    const int* dst = eidx + N_EDGES;

    int nb_n = (N_NODES + 255) / 256;
    int nb_e = (N_EDGES + 255) / 256;

    init_kernel<<<nb_n, 256>>>();
    count_kernel<<<nb_e, 256>>>(dst);
    scan1_kernel<<<SCAN_NBLK, SCAN_BLOCK>>>();
    scan2_kernel<<<1, 128>>>();
    scan3_kernel<<<SCAN_NBLK, SCAN_BLOCK>>>();
    fill_self_kernel<<<nb_n, 256>>>();
    fill_edges_kernel<<<nb_e, 256>>>(src, dst);

    mlp0_kernel<<<nb_n, 256>>>(x, nidx, emb, W1, b1);

    int nb_c = (N_NODES + 7) / 8;   // warp per node, 8 warps/block
    conv_kernel<1><<<nb_c, 256>>>(Wq + 0,  bq + 0,  Wk + 0,  bk + 0,  Wv + 0,  bv + 0);
    conv_kernel<2><<<nb_c, 256>>>(Wq + 8,  bq + 8,  Wk + 8,  bk + 8,  Wv + 8,  bv + 8);
    conv_kernel<3><<<nb_c, 256>>>(Wq + 16, bq + 16, Wk + 16, bk + 16, Wv + 16, bv + 16);

    out_kernel<<<nb_n, 256>>>(W2, b2, out);
}